// round 16
// baseline (speedup 1.0000x reference)
#include <cuda_runtime.h>

#define TPB 512
#define NBLK 148                    // one block per SM, all co-resident
#define NBH7 136                    // blocks 0..135: H=7 (14 cells/thr); rest H=6
#define NXFIX (1 << 20)             // 136*512*14 + 12*512*12 = 1048576
#define NSTEPS 32
#define NGRP 10                     // arrive tree: 9 groups of 16 + 1 group of 4

typedef unsigned long long ull;

__device__ float4 g_haloL[2][NBLK];   // block's first cell (r,m,E)
__device__ float4 g_haloR[2][NBLK];   // block's last cell
__device__ unsigned int g_gmax[NGRP]; // per-group wavespeed max (bits)
__device__ unsigned int g_gcnt[NGRP]; // per-group arrival counters
__device__ unsigned int g_maxbits;    // global max (bits)
__device__ unsigned int g_arrive2;    // group-leader arrival counter
__device__ volatile unsigned int g_release;
__device__ float g_t;
__device__ float g_dtdx;

__global__ void pre_kernel() {
    for (int i = 0; i < NGRP; i++) { g_gmax[i] = 0u; g_gcnt[i] = 0u; }
    g_maxbits = 0u;
    g_arrive2 = 0u;
    g_release = 0u;
    g_t = 0.0f;
}

// ---------------- packed f32x2 primitives ----------------
__device__ __forceinline__ ull pk2(float lo, float hi) {
    ull r; asm("mov.b64 %0, {%1, %2};" : "=l"(r) : "f"(lo), "f"(hi)); return r;
}
__device__ __forceinline__ void up2(ull v, float& lo, float& hi) {
    asm("mov.b64 {%0, %1}, %2;" : "=f"(lo), "=f"(hi) : "l"(v));
}
__device__ __forceinline__ float lo2(ull v) { float a, b; up2(v, a, b); return a; }
__device__ __forceinline__ float hi2(ull v) { float a, b; up2(v, a, b); return b; }
__device__ __forceinline__ ull bc2(float x) {
    unsigned int u = __float_as_uint(x);
    return ((ull)u << 32) | (ull)u;
}
__device__ __forceinline__ ull f2add(ull a, ull b) {
    ull r; asm("add.rn.f32x2 %0, %1, %2;" : "=l"(r) : "l"(a), "l"(b)); return r;
}
__device__ __forceinline__ ull f2mul(ull a, ull b) {
    ull r; asm("mul.rn.f32x2 %0, %1, %2;" : "=l"(r) : "l"(a), "l"(b)); return r;
}
__device__ __forceinline__ ull f2fma(ull a, ull b, ull c) {
    ull r; asm("fma.rn.f32x2 %0, %1, %2, %3;" : "=l"(r) : "l"(a), "l"(b), "l"(c));
    return r;
}
__device__ __forceinline__ ull f2sub(ull a, ull b) { return f2fma(b, bc2(-1.0f), a); }
__device__ __forceinline__ ull f2rsq(ull x) {
    float a, b; up2(x, a, b);
    return pk2(rsqrtf(a), rsqrtf(b));
}
__device__ __forceinline__ ull f2sqrt(ull x) {   // MUFU.SQRT per lane
    float a, b; up2(x, a, b);
    float ra, rb;
    asm("sqrt.approx.f32 %0, %1;" : "=f"(ra) : "f"(a));
    asm("sqrt.approx.f32 %0, %1;" : "=f"(rb) : "f"(b));
    return pk2(ra, rb);
}
__device__ __forceinline__ ull f2rcp(ull x) {
    float a, b; up2(x, a, b);
    float ra, rb;
    asm("rcp.approx.f32 %0, %1;" : "=f"(ra) : "f"(a));
    asm("rcp.approx.f32 %0, %1;" : "=f"(rb) : "f"(b));
    return pk2(ra, rb);
}

__device__ __forceinline__ float fsqrt_fast(float x) { return x * rsqrtf(x); }

// ---------------- scalar cell/flux (edge fixups only) ----------------
struct Cell { float r, m, E, u, p, q, H; };

__device__ __forceinline__ Cell derive(float r, float m, float E) {
    Cell c;
    float s = rsqrtf(r);
    float ir = s * s;
    c.r = r; c.m = m; c.E = E;
    c.u = m * ir;
    c.p = 0.4f * (E - 0.5f * m * c.u);
    c.q = r * s;
    c.H = (E + c.p) * ir;
    return c;
}

__device__ __forceinline__ float3 roe_flux(const Cell& L, const Cell& R) {
    float rcp;
    asm("rcp.approx.f32 %0, %1;" : "=f"(rcp) : "f"(L.q + R.q));
    float ur = (L.q * L.u + R.q * R.u) * rcp;
    float Hr = (L.q * L.H + R.q * R.H) * rcp;
    float c2 = fmaxf(0.4f * (Hr - 0.5f * ur * ur), 1e-10f);
    float cinv = rsqrtf(c2);
    float c = c2 * cinv;
    float ic2 = cinv * cinv;
    float e2 = 0.01f * c2;
    float l1 = ur - c, l3 = ur + c;
    float a1 = fsqrt_fast(l1 * l1 + e2);
    float a2 = fsqrt_fast(ur * ur + e2);
    float a3 = fsqrt_fast(l3 * l3 + e2);
    float drho = R.r - L.r, du = R.u - L.u, dp = R.p - L.p;
    float h = 0.5f * ic2;
    float crdu = c * R.r * du;
    float b1 = a1 * ((dp - crdu) * h);
    float b3 = a3 * ((dp + crdu) * h);
    float b2 = a2 * (drho - dp * ic2);
    float uc = ur * c;
    float3 F;
    F.x = 0.5f * (L.m + R.m - (b1 + b2 + b3));
    F.y = 0.5f * ((L.m * L.u + L.p) + (R.m * R.u + R.p)
                  - (b1 * l1 + b2 * ur + b3 * l3));
    F.z = 0.5f * (L.u * (L.E + L.p) + R.u * (R.E + R.p)
                  - (b1 * (Hr - uc) + b2 * (0.5f * ur * ur) + b3 * (Hr + uc)));
    return F;
}

// ---------------- packed cell/flux ----------------
struct Cell2 { ull r, m, E, u, p, q, H; };
struct Flux2 { ull x, y, z; };

__device__ __forceinline__ Cell2 derive2(ull r, ull m, ull E) {
    Cell2 c;
    ull s = f2rsq(r);
    ull ir = f2mul(s, s);
    c.r = r; c.m = m; c.E = E;
    c.u = f2mul(m, ir);
    ull mu = f2mul(m, c.u);
    c.p = f2mul(bc2(0.4f), f2fma(mu, bc2(-0.5f), E));
    c.q = f2mul(r, s);
    c.H = f2mul(f2add(E, c.p), ir);
    return c;
}

__device__ __forceinline__ Flux2 roe_flux2(const Cell2& L, const Cell2& R) {
    ull rd = f2rcp(f2add(L.q, R.q));
    ull ur = f2mul(f2fma(L.q, L.u, f2mul(R.q, R.u)), rd);
    ull Hr = f2mul(f2fma(L.q, L.H, f2mul(R.q, R.H)), rd);
    ull u2 = f2mul(ur, ur);
    ull c2 = f2mul(bc2(0.4f), f2fma(u2, bc2(-0.5f), Hr));
    float c2a, c2b; up2(c2, c2a, c2b);
    c2a = fmaxf(c2a, 1e-10f); c2b = fmaxf(c2b, 1e-10f);
    ull c2c = pk2(c2a, c2b);
    ull cinv = pk2(rsqrtf(c2a), rsqrtf(c2b));
    ull c = f2mul(c2c, cinv);
    ull ic2 = f2mul(cinv, cinv);
    ull e2 = f2mul(bc2(0.01f), c2c);
    ull l1 = f2sub(ur, c);
    ull l3 = f2add(ur, c);
    ull a1 = f2sqrt(f2fma(l1, l1, e2));
    ull a2 = f2sqrt(f2add(u2, e2));
    ull a3 = f2sqrt(f2fma(l3, l3, e2));
    ull dp = f2sub(R.p, L.p);
    ull h = f2mul(bc2(0.5f), ic2);
    ull crdu = f2mul(f2mul(c, R.r), f2sub(R.u, L.u));
    ull b1 = f2mul(a1, f2mul(f2sub(dp, crdu), h));
    ull b3 = f2mul(a3, f2mul(f2add(dp, crdu), h));
    ull b2 = f2mul(a2, f2sub(f2sub(R.r, L.r), f2mul(dp, ic2)));
    ull uc = f2mul(ur, c);
    Flux2 F;
    F.x = f2mul(bc2(0.5f), f2sub(f2add(L.m, R.m), f2add(f2add(b1, b2), b3)));
    ull dm = f2fma(b1, l1, f2fma(b3, l3, f2mul(b2, ur)));
    ull Fm = f2add(f2fma(L.m, L.u, L.p), f2fma(R.m, R.u, R.p));
    F.y = f2mul(bc2(0.5f), f2sub(Fm, dm));
    ull hu2 = f2mul(bc2(0.5f), u2);
    ull de = f2fma(b1, f2sub(Hr, uc), f2fma(b3, f2add(Hr, uc), f2mul(b2, hu2)));
    ull Fe = f2add(f2mul(L.u, f2add(L.E, L.p)), f2mul(R.u, f2add(R.E, R.p)));
    F.z = f2mul(bc2(0.5f), f2sub(Fe, de));
    return F;
}

// Packed max wavespeed (two cells) from conserved -> scalar max.
__device__ __forceinline__ float wavespd2(ull r2, ull m2, ull E2) {
    ull s = f2rsq(r2);
    ull ir = f2mul(s, s);
    ull u = f2mul(m2, ir);
    ull mu = f2mul(m2, u);
    ull p = f2mul(bc2(0.4f), f2fma(mu, bc2(-0.5f), E2));
    ull cc = f2sqrt(f2mul(bc2(1.4f), f2mul(p, ir)));
    ull au;
    asm("and.b64 %0, %1, %2;" : "=l"(au) : "l"(u), "l"(0x7FFFFFFF7FFFFFFFULL));
    ull sp = f2add(au, cc);
    float a, b; up2(sp, a, b);
    return fmaxf(a, b);
}
// Wavespeed from an already-derived pair: |u| + sqrt(0.4*(H - u^2/2)) = |u|+c.
__device__ __forceinline__ float wavespd2_uh(ull u, ull H) {
    ull u2 = f2mul(u, u);
    ull c2 = f2mul(bc2(0.4f), f2fma(u2, bc2(-0.5f), H));
    ull cc = f2sqrt(c2);
    ull au;
    asm("and.b64 %0, %1, %2;" : "=l"(au) : "l"(u), "l"(0x7FFFFFFF7FFFFFFFULL));
    ull sp = f2add(au, cc);
    float a, b; up2(sp, a, b);
    return fmaxf(a, b);
}

// tid==0 only, after the spd sync. NON-BLOCKING two-level arrive:
// block -> group slot (<=16-deep atomic chains, parallel across groups),
// group finisher -> global (10-deep chain); last group finisher computes dt.
__device__ __forceinline__ void block_arrive(const float* tf, unsigned int epoch,
                                             const unsigned int* swm, int b) {
    unsigned int m = swm[0];
#pragma unroll
    for (int w = 1; w < TPB / 32; w++) m = max(m, swm[w]);
    const int g = b >> 4;
    const unsigned int gsize = (g == NGRP - 1) ? (NBLK - 16 * (NGRP - 1)) : 16u;
    atomicMax(&g_gmax[g], m);
    __threadfence();
    if (atomicAdd(&g_gcnt[g], 1u) == gsize - 1) {
        unsigned int gm = g_gmax[g];          // all group arrivals visible
        atomicMax(&g_maxbits, gm);
        __threadfence();
        if (atomicAdd(&g_arrive2, 1u) == NGRP - 1) {
            float mx = __uint_as_float(g_maxbits);
            float t = *(volatile float*)&g_t;
            float dt = fminf(5e-4f / mx, fmaxf(__ldcg(tf) - t, 0.0f));
            *(volatile float*)&g_t = t + dt;
            *(volatile float*)&g_dtdx = dt * 1000.0f;
#pragma unroll
            for (int i = 0; i < NGRP; i++) { g_gmax[i] = 0u; g_gcnt[i] = 0u; }
            g_maxbits = 0u;
            g_arrive2 = 0u;
            __threadfence();
            g_release = epoch;
        }
    }
}

// Thread t owns two chains of H cells: lo = [bb + t*H), hi = [bb + TPB*H + t*H).
// Per step: spd(current)+arrive EARLY -> F0..F3 (dv cells 0..2) overlap the dt
// reduction -> wait -> stream cells 3..H-1 -> publish. R11/R14 edge topology.
template <int H>
__device__ __forceinline__ void run_solver(
    const float* __restrict__ rho, const float* __restrict__ uin,
    const float* __restrict__ pin, const float* __restrict__ tf,
    float* __restrict__ out, int n, int bb, int b,
    ull* sdr, ull* sdm, ull* sdE, ull* sdu, ull* sdp, ull* sdq, ull* sdh,
    ull* sfx, ull* sfy, ull* sfz,
    unsigned int* swm, float* s_dt) {
    const int tid = threadIdx.x;
    const int iL = bb + tid * H;
    const int iH = bb + TPB * H + tid * H;

    ull r[H], m[H], E[H];

    // ---- init: conserved (both lanes), halos(parity0), sd2 = LAST derived ----
#pragma unroll
    for (int k = 0; k < H; k++) {
        float rl = rho[iL + k], ul = uin[iL + k], pl = pin[iL + k];
        float rh = rho[iH + k], uh = uin[iH + k], ph = pin[iH + k];
        float ml = rl * ul, mh = rh * uh;
        r[k] = pk2(rl, rh);
        m[k] = pk2(ml, mh);
        E[k] = pk2(pl * 2.5f + 0.5f * ml * ul, ph * 2.5f + 0.5f * mh * uh);
    }
    if (tid == 0)
        __stcg(&g_haloL[0][b], make_float4(lo2(r[0]), lo2(m[0]), lo2(E[0]), 0.0f));
    if (tid == TPB - 1) {
        __stcg(&g_haloR[0][b],
               make_float4(hi2(r[H - 1]), hi2(m[H - 1]), hi2(E[H - 1]), 0.0f));
        __threadfence();
    }
    {
        Cell2 Dn = derive2(r[H - 1], m[H - 1], E[H - 1]);
        sdr[tid] = Dn.r; sdm[tid] = Dn.m; sdE[tid] = Dn.E; sdu[tid] = Dn.u;
        sdp[tid] = Dn.p; sdq[tid] = Dn.q; sdh[tid] = Dn.H;
    }

    // ---- 32 persistent steps ----
    for (int s = 0; s < NSTEPS; s++) {
        const int rb = s & 1;

        // === Stage 1: spd of CURRENT state, arrive EARLY ===
        {
            // Last cell from own sd (already derived): 2 MUFU instead of 4.
            float spd = wavespd2_uh(sdu[tid], sdh[tid]);
#pragma unroll
            for (int k = 0; k < H - 1; k++)
                spd = fmaxf(spd, wavespd2(r[k], m[k], E[k]));
            unsigned int bits = __reduce_max_sync(0xffffffffu, __float_as_uint(spd));
            if ((tid & 31) == 0) swm[tid >> 5] = bits;
            __syncthreads();                       // also orders sd writes->reads
            if (tid == 0) block_arrive(tf, (unsigned int)(s + 1), swm, b);
        }

        // === Stage 2 (dt-independent): F0..F3, dv for cells 0..2 ===
        Cell2 D0 = derive2(r[0], m[0], E[0]);
        Cell2 L;
        if (tid > 0) {
            L.r = sdr[tid - 1]; L.m = sdm[tid - 1]; L.E = sdE[tid - 1];
            L.u = sdu[tid - 1]; L.p = sdp[tid - 1]; L.q = sdq[tid - 1];
            L.H = sdh[tid - 1];
        } else {
            // lo: provisional replicate (exact for b==0; additive fixup post-wait
            //     for b>0).  hi: lo-chain last of thread TPB-1 (mid-block face).
            L.r = pk2(lo2(D0.r), lo2(sdr[TPB - 1]));
            L.m = pk2(lo2(D0.m), lo2(sdm[TPB - 1]));
            L.E = pk2(lo2(D0.E), lo2(sdE[TPB - 1]));
            L.u = pk2(lo2(D0.u), lo2(sdu[TPB - 1]));
            L.p = pk2(lo2(D0.p), lo2(sdp[TPB - 1]));
            L.q = pk2(lo2(D0.q), lo2(sdq[TPB - 1]));
            L.H = pk2(lo2(D0.H), lo2(sdh[TPB - 1]));
        }
        Flux2 F0 = roe_flux2(L, D0);
        sfx[tid] = F0.x; sfy[tid] = F0.y; sfz[tid] = F0.z;
        const float f0px = lo2(F0.x), f0py = lo2(F0.y), f0pz = lo2(F0.z);

        Flux2 Fp = F0;
        Cell2 Dp = D0;
        ull dvx[3], dvy[3], dvz[3];               // dv of cells 0..2
#pragma unroll
        for (int k = 1; k <= 3; k++) {            // k=1..3 < H-1 (H>=6)
            Cell2 Dk = derive2(r[k], m[k], E[k]);
            Flux2 Fk = roe_flux2(Dp, Dk);
            dvx[k - 1] = f2sub(Fk.x, Fp.x);
            dvy[k - 1] = f2sub(Fk.y, Fp.y);
            dvz[k - 1] = f2sub(Fk.z, Fp.z);
            Dp = Dk;
            Fp = Fk;
        }
        // here: Fp = F3, Dp = D3

        // === Stage 3: wait for this step's dt (hidden by Stage 1+2) ===
        if (tid == 0) {
            while (g_release < (unsigned int)(s + 1)) {}
            __threadfence();
            *s_dt = __ldcg(&g_dtdx);
        }
        __syncthreads();
        const float dtdx = *s_dt;
        const ull nd = pk2(-dtdx, -dtdx);

        // === Stage 4: fixup, apply dv, stream cells 3..H-1, publish ===
        // tid0/b>0: additive fixup of cell-0 lo-lane dv using OLD state.
        if (tid == 0 && b > 0) {
            float4 gl = __ldcg(&g_haloR[rb][b - 1]);
            Cell dgl = derive(gl.x, gl.y, gl.z);
            Cell d0 = derive(lo2(r[0]), lo2(m[0]), lo2(E[0]));   // pre-update
            float3 f0n = roe_flux(dgl, d0);
            dvx[0] = pk2(lo2(dvx[0]) + (f0px - f0n.x), hi2(dvx[0]));
            dvy[0] = pk2(lo2(dvy[0]) + (f0py - f0n.y), hi2(dvy[0]));
            dvz[0] = pk2(lo2(dvz[0]) + (f0pz - f0n.z), hi2(dvz[0]));
        }
#pragma unroll
        for (int k = 0; k < 3; k++) {
            r[k] = f2fma(dvx[k], nd, r[k]);
            m[k] = f2fma(dvy[k], nd, m[k]);
            E[k] = f2fma(dvz[k], nd, E[k]);
        }

        // Stream cells 3..H-2 (derive pre-update state, flux, update cell k-1).
#pragma unroll
        for (int k = 4; k < H; k++) {
            Cell2 Dk;
            if (k == H - 1) {   // own last-cell derived, cached in shared
                Dk.r = sdr[tid]; Dk.m = sdm[tid]; Dk.E = sdE[tid];
                Dk.u = sdu[tid]; Dk.p = sdp[tid]; Dk.q = sdq[tid];
                Dk.H = sdh[tid];
            } else {
                Dk = derive2(r[k], m[k], E[k]);
            }
            Flux2 Fk = roe_flux2(Dp, Dk);
            r[k - 1] = f2fma(f2sub(Fk.x, Fp.x), nd, r[k - 1]);
            m[k - 1] = f2fma(f2sub(Fk.y, Fp.y), nd, m[k - 1]);
            E[k - 1] = f2fma(f2sub(Fk.z, Fp.z), nd, E[k - 1]);
            Dp = Dk;
            Fp = Fk;
        }
        // here: Fp = F_{H-1}, Dp = own last-cell derived pair (pre-update)

        // Right face of last cells: neighbor's F0 (written pre-wait, ordered by
        // the Stage-3 sync), or mid-block/cross-block construction at tid max.
        Flux2 FH;
        if (tid < TPB - 1) {
            FH.x = sfx[tid + 1]; FH.y = sfy[tid + 1]; FH.z = sfz[tid + 1];
        } else {
            Cell dL;
            dL.r = hi2(Dp.r); dL.m = hi2(Dp.m); dL.E = hi2(Dp.E);
            dL.u = hi2(Dp.u); dL.p = hi2(Dp.p); dL.q = hi2(Dp.q); dL.H = hi2(Dp.H);
            Cell dR;
            if (b < NBLK - 1) {
                float4 gr = __ldcg(&g_haloL[rb][b + 1]);
                dR = derive(gr.x, gr.y, gr.z);
            } else {
                dR = dL;   // domain-right replicated ghost
            }
            float3 fs = roe_flux(dL, dR);
            FH.x = pk2(hi2(sfx[0]), fs.x);
            FH.y = pk2(hi2(sfy[0]), fs.y);
            FH.z = pk2(hi2(sfz[0]), fs.z);
        }
        r[H - 1] = f2fma(f2sub(FH.x, Fp.x), nd, r[H - 1]);
        m[H - 1] = f2fma(f2sub(FH.y, Fp.y), nd, m[H - 1]);
        E[H - 1] = f2fma(f2sub(FH.z, Fp.z), nd, E[H - 1]);

        if (s + 1 < NSTEPS) {
            if (tid == 0)
                __stcg(&g_haloL[rb ^ 1][b],
                       make_float4(lo2(r[0]), lo2(m[0]), lo2(E[0]), 0.0f));
            if (tid == TPB - 1) {
                __stcg(&g_haloR[rb ^ 1][b],
                       make_float4(hi2(r[H - 1]), hi2(m[H - 1]), hi2(E[H - 1]), 0.0f));
                __threadfence();
            }
            // Publish new last-cell derived pair (own slot; read next step
            // after its Stage-1 sync).
            Cell2 Dn = derive2(r[H - 1], m[H - 1], E[H - 1]);
            sdr[tid] = Dn.r; sdm[tid] = Dn.m; sdE[tid] = Dn.E; sdu[tid] = Dn.u;
            sdp[tid] = Dn.p; sdq[tid] = Dn.q; sdh[tid] = Dn.H;
        }
    }

    // ---- final: conserved -> primitives, both lanes ----
#pragma unroll
    for (int k = 0; k < H; k++) {
        float rl, rh, ml, mh, El, Eh;
        up2(r[k], rl, rh); up2(m[k], ml, mh); up2(E[k], El, Eh);
        float sl = rsqrtf(rl), sh = rsqrtf(rh);
        float il = sl * sl, ih = sh * sh;
        float ul = ml * il, uh = mh * ih;
        out[iL + k] = rl;
        out[n + iL + k] = ul;
        out[2 * n + iL + k] = 0.4f * (El - 0.5f * ml * ul);
        out[iH + k] = rh;
        out[n + iH + k] = uh;
        out[2 * n + iH + k] = 0.4f * (Eh - 0.5f * mh * uh);
    }
}

__global__ void __launch_bounds__(TPB, 1) euler_kernel(
    const float* __restrict__ rho, const float* __restrict__ uin,
    const float* __restrict__ pin, const float* __restrict__ tf,
    float* __restrict__ out, int n) {
    __shared__ ull sdr[TPB], sdm[TPB], sdE[TPB], sdu[TPB],
                   sdp[TPB], sdq[TPB], sdh[TPB];
    __shared__ ull sfx[TPB], sfy[TPB], sfz[TPB];
    __shared__ unsigned int swm[TPB / 32];
    __shared__ float s_dt;

    const int b = blockIdx.x;
    if (b < NBH7) {
        int bb = b * (TPB * 14);
        run_solver<7>(rho, uin, pin, tf, out, n, bb, b,
                      sdr, sdm, sdE, sdu, sdp, sdq, sdh, sfx, sfy, sfz, swm, &s_dt);
    } else {
        int bb = NBH7 * (TPB * 14) + (b - NBH7) * (TPB * 12);
        run_solver<6>(rho, uin, pin, tf, out, n, bb, b,
                      sdr, sdm, sdE, sdu, sdp, sdq, sdh, sfx, sfy, sfz, swm, &s_dt);
    }
}

extern "C" void kernel_launch(void* const* d_in, const int* in_sizes, int n_in,
                              void* d_out, int out_size) {
    const float* rho = (const float*)d_in[0];
    const float* u = (const float*)d_in[1];
    const float* p = (const float*)d_in[2];
    const float* tf = (const float*)d_in[3];
    float* out = (float*)d_out;
    int n = in_sizes[0];
    if (n != NXFIX) return;   // problem is fixed at NX = 2^20

    pre_kernel<<<1, 1>>>();
    euler_kernel<<<NBLK, TPB>>>(rho, u, p, tf, out, n);
}

// round 17
// speedup vs baseline: 1.2351x; 1.2351x over previous
#include <cuda_runtime.h>

#define TPB 512
#define NBLK 148                    // one block per SM, all co-resident
#define NBH7 136                    // blocks 0..135: H=7 (14 cells/thr); rest H=6
#define NXFIX (1 << 20)             // 136*512*14 + 12*512*12 = 1048576
#define NSTEPS 32

typedef unsigned long long ull;

__device__ float4 g_haloL[2][NBLK];   // block's first cell (r,m,E)
__device__ float4 g_haloR[2][NBLK];   // block's last cell
__device__ unsigned int g_maxbits;
__device__ unsigned int g_arrive;
__device__ volatile unsigned int g_release;
__device__ float g_t;
__device__ float g_dtdx;
__device__ float g_tf;                // cached t_final

__global__ void pre_kernel(const float* tf) {
    g_maxbits = 0u;
    g_arrive = 0u;
    g_release = 0u;
    g_t = 0.0f;
    g_tf = *tf;
}

// ---------------- packed f32x2 primitives ----------------
__device__ __forceinline__ ull pk2(float lo, float hi) {
    ull r; asm("mov.b64 %0, {%1, %2};" : "=l"(r) : "f"(lo), "f"(hi)); return r;
}
__device__ __forceinline__ void up2(ull v, float& lo, float& hi) {
    asm("mov.b64 {%0, %1}, %2;" : "=f"(lo), "=f"(hi) : "l"(v));
}
__device__ __forceinline__ float lo2(ull v) { float a, b; up2(v, a, b); return a; }
__device__ __forceinline__ float hi2(ull v) { float a, b; up2(v, a, b); return b; }
__device__ __forceinline__ ull bc2(float x) {
    unsigned int u = __float_as_uint(x);
    return ((ull)u << 32) | (ull)u;
}
__device__ __forceinline__ ull f2add(ull a, ull b) {
    ull r; asm("add.rn.f32x2 %0, %1, %2;" : "=l"(r) : "l"(a), "l"(b)); return r;
}
__device__ __forceinline__ ull f2mul(ull a, ull b) {
    ull r; asm("mul.rn.f32x2 %0, %1, %2;" : "=l"(r) : "l"(a), "l"(b)); return r;
}
__device__ __forceinline__ ull f2fma(ull a, ull b, ull c) {
    ull r; asm("fma.rn.f32x2 %0, %1, %2, %3;" : "=l"(r) : "l"(a), "l"(b), "l"(c));
    return r;
}
__device__ __forceinline__ ull f2sub(ull a, ull b) { return f2fma(b, bc2(-1.0f), a); }
__device__ __forceinline__ ull f2rsq(ull x) {
    float a, b; up2(x, a, b);
    return pk2(rsqrtf(a), rsqrtf(b));
}
__device__ __forceinline__ ull f2sqrt(ull x) {   // MUFU.SQRT per lane
    float a, b; up2(x, a, b);
    float ra, rb;
    asm("sqrt.approx.f32 %0, %1;" : "=f"(ra) : "f"(a));
    asm("sqrt.approx.f32 %0, %1;" : "=f"(rb) : "f"(b));
    return pk2(ra, rb);
}
__device__ __forceinline__ ull f2rcp(ull x) {
    float a, b; up2(x, a, b);
    float ra, rb;
    asm("rcp.approx.f32 %0, %1;" : "=f"(ra) : "f"(a));
    asm("rcp.approx.f32 %0, %1;" : "=f"(rb) : "f"(b));
    return pk2(ra, rb);
}

__device__ __forceinline__ float fsqrt_fast(float x) { return x * rsqrtf(x); }

// ---------------- scalar cell/flux (edge fixups only) ----------------
struct Cell { float r, m, E, u, p, q, H; };

__device__ __forceinline__ Cell derive(float r, float m, float E) {
    Cell c;
    float s = rsqrtf(r);
    float ir = s * s;
    c.r = r; c.m = m; c.E = E;
    c.u = m * ir;
    c.p = 0.4f * (E - 0.5f * m * c.u);
    c.q = r * s;
    c.H = (E + c.p) * ir;
    return c;
}

__device__ __forceinline__ float3 roe_flux(const Cell& L, const Cell& R) {
    float rcp;
    asm("rcp.approx.f32 %0, %1;" : "=f"(rcp) : "f"(L.q + R.q));
    float ur = (L.q * L.u + R.q * R.u) * rcp;
    float Hr = (L.q * L.H + R.q * R.H) * rcp;
    float c2 = fmaxf(0.4f * (Hr - 0.5f * ur * ur), 1e-10f);
    float cinv = rsqrtf(c2);
    float c = c2 * cinv;
    float ic2 = cinv * cinv;
    float e2 = 0.01f * c2;
    float l1 = ur - c, l3 = ur + c;
    float a1 = fsqrt_fast(l1 * l1 + e2);
    float a2 = fsqrt_fast(ur * ur + e2);
    float a3 = fsqrt_fast(l3 * l3 + e2);
    float drho = R.r - L.r, du = R.u - L.u, dp = R.p - L.p;
    float h = 0.5f * ic2;
    float crdu = c * R.r * du;
    float b1 = a1 * ((dp - crdu) * h);
    float b3 = a3 * ((dp + crdu) * h);
    float b2 = a2 * (drho - dp * ic2);
    float uc = ur * c;
    float3 F;
    F.x = 0.5f * (L.m + R.m - (b1 + b2 + b3));
    F.y = 0.5f * ((L.m * L.u + L.p) + (R.m * R.u + R.p)
                  - (b1 * l1 + b2 * ur + b3 * l3));
    F.z = 0.5f * (L.u * (L.E + L.p) + R.u * (R.E + R.p)
                  - (b1 * (Hr - uc) + b2 * (0.5f * ur * ur) + b3 * (Hr + uc)));
    return F;
}

// ---------------- packed cell/flux ----------------
struct Cell2 { ull r, m, E, u, p, q, H; };
struct Flux2 { ull x, y, z; };

__device__ __forceinline__ Cell2 derive2(ull r, ull m, ull E) {
    Cell2 c;
    ull s = f2rsq(r);
    ull ir = f2mul(s, s);
    c.r = r; c.m = m; c.E = E;
    c.u = f2mul(m, ir);
    ull mu = f2mul(m, c.u);
    c.p = f2mul(bc2(0.4f), f2fma(mu, bc2(-0.5f), E));
    c.q = f2mul(r, s);
    c.H = f2mul(f2add(E, c.p), ir);
    return c;
}

__device__ __forceinline__ Flux2 roe_flux2(const Cell2& L, const Cell2& R) {
    ull rd = f2rcp(f2add(L.q, R.q));
    ull ur = f2mul(f2fma(L.q, L.u, f2mul(R.q, R.u)), rd);
    ull Hr = f2mul(f2fma(L.q, L.H, f2mul(R.q, R.H)), rd);
    ull u2 = f2mul(ur, ur);
    ull c2 = f2mul(bc2(0.4f), f2fma(u2, bc2(-0.5f), Hr));
    float c2a, c2b; up2(c2, c2a, c2b);
    c2a = fmaxf(c2a, 1e-10f); c2b = fmaxf(c2b, 1e-10f);
    ull c2c = pk2(c2a, c2b);
    ull cinv = pk2(rsqrtf(c2a), rsqrtf(c2b));
    ull c = f2mul(c2c, cinv);
    ull ic2 = f2mul(cinv, cinv);
    ull e2 = f2mul(bc2(0.01f), c2c);
    ull l1 = f2sub(ur, c);
    ull l3 = f2add(ur, c);
    ull a1 = f2sqrt(f2fma(l1, l1, e2));
    ull a2 = f2sqrt(f2add(u2, e2));
    ull a3 = f2sqrt(f2fma(l3, l3, e2));
    ull dp = f2sub(R.p, L.p);
    ull h = f2mul(bc2(0.5f), ic2);
    ull crdu = f2mul(f2mul(c, R.r), f2sub(R.u, L.u));
    ull b1 = f2mul(a1, f2mul(f2sub(dp, crdu), h));
    ull b3 = f2mul(a3, f2mul(f2add(dp, crdu), h));
    ull b2 = f2mul(a2, f2sub(f2sub(R.r, L.r), f2mul(dp, ic2)));
    ull uc = f2mul(ur, c);
    Flux2 F;
    F.x = f2mul(bc2(0.5f), f2sub(f2add(L.m, R.m), f2add(f2add(b1, b2), b3)));
    ull dm = f2fma(b1, l1, f2fma(b3, l3, f2mul(b2, ur)));
    ull Fm = f2add(f2fma(L.m, L.u, L.p), f2fma(R.m, R.u, R.p));
    F.y = f2mul(bc2(0.5f), f2sub(Fm, dm));
    ull hu2 = f2mul(bc2(0.5f), u2);
    ull de = f2fma(b1, f2sub(Hr, uc), f2fma(b3, f2add(Hr, uc), f2mul(b2, hu2)));
    ull Fe = f2add(f2mul(L.u, f2add(L.E, L.p)), f2mul(R.u, f2add(R.E, R.p)));
    F.z = f2mul(bc2(0.5f), f2sub(Fe, de));
    return F;
}

// Packed max wavespeed (two cells) from conserved -> scalar max.
__device__ __forceinline__ float wavespd2(ull r2, ull m2, ull E2) {
    ull s = f2rsq(r2);
    ull ir = f2mul(s, s);
    ull u = f2mul(m2, ir);
    ull mu = f2mul(m2, u);
    ull p = f2mul(bc2(0.4f), f2fma(mu, bc2(-0.5f), E2));
    ull cc = f2sqrt(f2mul(bc2(1.4f), f2mul(p, ir)));
    ull au;
    asm("and.b64 %0, %1, %2;" : "=l"(au) : "l"(u), "l"(0x7FFFFFFF7FFFFFFFULL));
    ull sp = f2add(au, cc);
    float a, b; up2(sp, a, b);
    return fmaxf(a, b);
}
// Wavespeed from an already-derived pair: |u| + sqrt(0.4*(H - u^2/2)) = |u|+c.
__device__ __forceinline__ float wavespd2_uh(ull u, ull H) {
    ull u2 = f2mul(u, u);
    ull c2 = f2mul(bc2(0.4f), f2fma(u2, bc2(-0.5f), H));
    ull cc = f2sqrt(c2);
    ull au;
    asm("and.b64 %0, %1, %2;" : "=l"(au) : "l"(u), "l"(0x7FFFFFFF7FFFFFFFULL));
    ull sp = f2add(au, cc);
    float a, b; up2(sp, a, b);
    return fmaxf(a, b);
}

// tid==0 only, after the spd sync. NON-BLOCKING arrive (R15-proven single level).
__device__ __forceinline__ void block_arrive(unsigned int epoch,
                                             const unsigned int* swm) {
    unsigned int m = swm[0];
#pragma unroll
    for (int w = 1; w < TPB / 32; w++) m = max(m, swm[w]);
    atomicMax(&g_maxbits, m);
    __threadfence();
    unsigned int a = atomicAdd(&g_arrive, 1u);
    if (a == NBLK - 1) {
        float mx = __uint_as_float(g_maxbits);
        float t = *(volatile float*)&g_t;
        float dt = fminf(5e-4f / mx, fmaxf(g_tf - t, 0.0f));
        *(volatile float*)&g_t = t + dt;
        *(volatile float*)&g_dtdx = dt * 1000.0f;
        g_maxbits = 0u;
        g_arrive = 0u;
        __threadfence();
        g_release = epoch;
    }
}

// Thread t owns two chains of H cells: lo = [bb + t*H), hi = [bb + TPB*H + t*H).
// Per step: (1) spd of CURRENT state -> arrive(s+1) FIRST, (2) dt-independent
// FULL flux chain overlaps the global dt reduction, (3) wait(s+1), update,
// publish. R11/R14/R15-proven edge topology (sd=last derived, sf=F0).
template <int H>
__device__ __forceinline__ void run_solver(
    const float* __restrict__ rho, const float* __restrict__ uin,
    const float* __restrict__ pin,
    float* __restrict__ out, int n, int bb, int b,
    ull* sdr, ull* sdm, ull* sdE, ull* sdu, ull* sdp, ull* sdq, ull* sdh,
    ull* sfx, ull* sfy, ull* sfz,
    unsigned int* swm, float* s_dt) {
    const int tid = threadIdx.x;
    const int iL = bb + tid * H;
    const int iH = bb + TPB * H + tid * H;

    ull r[H], m[H], E[H];

    // ---- init: conserved (both lanes), halos(parity0), sd2 = LAST derived ----
    // No arrive here: step 0's spd loop measures this same state.
#pragma unroll
    for (int k = 0; k < H; k++) {
        float rl = rho[iL + k], ul = uin[iL + k], pl = pin[iL + k];
        float rh = rho[iH + k], uh = uin[iH + k], ph = pin[iH + k];
        float ml = rl * ul, mh = rh * uh;
        r[k] = pk2(rl, rh);
        m[k] = pk2(ml, mh);
        E[k] = pk2(pl * 2.5f + 0.5f * ml * ul, ph * 2.5f + 0.5f * mh * uh);
    }
    if (tid == 0)
        __stcg(&g_haloL[0][b], make_float4(lo2(r[0]), lo2(m[0]), lo2(E[0]), 0.0f));
    if (tid == TPB - 1) {
        __stcg(&g_haloR[0][b],
               make_float4(hi2(r[H - 1]), hi2(m[H - 1]), hi2(E[H - 1]), 0.0f));
        __threadfence();
    }
    {
        Cell2 Dn = derive2(r[H - 1], m[H - 1], E[H - 1]);
        sdr[tid] = Dn.r; sdm[tid] = Dn.m; sdE[tid] = Dn.E; sdu[tid] = Dn.u;
        sdp[tid] = Dn.p; sdq[tid] = Dn.q; sdh[tid] = Dn.H;
    }

    // ---- 32 persistent steps ----
    for (int s = 0; s < NSTEPS; s++) {
        const int rb = s & 1;

        // === Stage 1: spd of CURRENT state, arrive EARLY ===
        {
            // Last cell from own sd (already derived): 2 MUFU instead of 4.
            float spd = wavespd2_uh(sdu[tid], sdh[tid]);
#pragma unroll
            for (int k = 0; k < H - 1; k++)
                spd = fmaxf(spd, wavespd2(r[k], m[k], E[k]));
            unsigned int bits = __reduce_max_sync(0xffffffffu, __float_as_uint(spd));
            if ((tid & 31) == 0) swm[tid >> 5] = bits;
            __syncthreads();                       // also orders sd writes->reads
            if (tid == 0) block_arrive((unsigned int)(s + 1), swm);
        }

        // === Stage 2 (dt-independent): FULL packed flux chain ===
        Cell2 D0 = derive2(r[0], m[0], E[0]);
        Cell2 L;
        if (tid > 0) {
            L.r = sdr[tid - 1]; L.m = sdm[tid - 1]; L.E = sdE[tid - 1];
            L.u = sdu[tid - 1]; L.p = sdp[tid - 1]; L.q = sdq[tid - 1];
            L.H = sdh[tid - 1];
        } else {
            // lo: provisional replicate (exact for b==0; additive fixup post-wait
            //     for b>0).  hi: lo-chain last of thread TPB-1 (mid-block face).
            L.r = pk2(lo2(D0.r), lo2(sdr[TPB - 1]));
            L.m = pk2(lo2(D0.m), lo2(sdm[TPB - 1]));
            L.E = pk2(lo2(D0.E), lo2(sdE[TPB - 1]));
            L.u = pk2(lo2(D0.u), lo2(sdu[TPB - 1]));
            L.p = pk2(lo2(D0.p), lo2(sdp[TPB - 1]));
            L.q = pk2(lo2(D0.q), lo2(sdq[TPB - 1]));
            L.H = pk2(lo2(D0.H), lo2(sdh[TPB - 1]));
        }
        Flux2 F0 = roe_flux2(L, D0);
        sfx[tid] = F0.x; sfy[tid] = F0.y; sfz[tid] = F0.z;
        const float f0px = lo2(F0.x), f0py = lo2(F0.y), f0pz = lo2(F0.z);

        Flux2 Fp = F0;
        Cell2 Dp = D0;
        ull dvx[H - 1], dvy[H - 1], dvz[H - 1];   // dv of cells 0..H-2
#pragma unroll
        for (int k = 1; k < H; k++) {
            Cell2 Dk;
            if (k == H - 1) {   // own last-cell derived, cached in shared
                Dk.r = sdr[tid]; Dk.m = sdm[tid]; Dk.E = sdE[tid];
                Dk.u = sdu[tid]; Dk.p = sdp[tid]; Dk.q = sdq[tid];
                Dk.H = sdh[tid];
            } else {
                Dk = derive2(r[k], m[k], E[k]);
            }
            Flux2 Fk = roe_flux2(Dp, Dk);
            dvx[k - 1] = f2sub(Fk.x, Fp.x);
            dvy[k - 1] = f2sub(Fk.y, Fp.y);
            dvz[k - 1] = f2sub(Fk.z, Fp.z);
            Dp = Dk;
            Fp = Fk;
        }
        // here: Fp = F_{H-1}, Dp = own last-cell derived pair (pre-update)

        // === Stage 3: wait for this step's dt (hidden by Stage 1+2) ===
        if (tid == 0) {
            while (g_release < (unsigned int)(s + 1)) {}
            __threadfence();
            *s_dt = __ldcg(&g_dtdx);
        }
        __syncthreads();
        const float dtdx = *s_dt;

        // === Stage 4: right faces, edge fixups, packed update, publish ===
        Flux2 FH;
        if (tid < TPB - 1) {
            FH.x = sfx[tid + 1]; FH.y = sfy[tid + 1]; FH.z = sfz[tid + 1];
        } else {
            // lo: mid-block face = tid 0's F0 hi lane.  hi: cross-block (scalar).
            Cell dL;
            dL.r = hi2(Dp.r); dL.m = hi2(Dp.m); dL.E = hi2(Dp.E);
            dL.u = hi2(Dp.u); dL.p = hi2(Dp.p); dL.q = hi2(Dp.q); dL.H = hi2(Dp.H);
            Cell dR;
            if (b < NBLK - 1) {
                float4 gr = __ldcg(&g_haloL[rb][b + 1]);
                dR = derive(gr.x, gr.y, gr.z);
            } else {
                dR = dL;   // domain-right replicated ghost
            }
            float3 fs = roe_flux(dL, dR);
            FH.x = pk2(hi2(sfx[0]), fs.x);
            FH.y = pk2(hi2(sfy[0]), fs.y);
            FH.z = pk2(hi2(sfz[0]), fs.z);
        }

        // tid0/b>0: additive fixup of cell-0 lo-lane dv using OLD state.
        if (tid == 0 && b > 0) {
            float4 gl = __ldcg(&g_haloR[rb][b - 1]);
            Cell dgl = derive(gl.x, gl.y, gl.z);
            Cell d0 = derive(lo2(r[0]), lo2(m[0]), lo2(E[0]));   // pre-update
            float3 f0n = roe_flux(dgl, d0);
            dvx[0] = pk2(lo2(dvx[0]) + (f0px - f0n.x), hi2(dvx[0]));
            dvy[0] = pk2(lo2(dvy[0]) + (f0py - f0n.y), hi2(dvy[0]));
            dvz[0] = pk2(lo2(dvz[0]) + (f0pz - f0n.z), hi2(dvz[0]));
        }

        const ull nd = pk2(-dtdx, -dtdx);
#pragma unroll
        for (int k = 0; k < H - 1; k++) {
            r[k] = f2fma(dvx[k], nd, r[k]);
            m[k] = f2fma(dvy[k], nd, m[k]);
            E[k] = f2fma(dvz[k], nd, E[k]);
        }
        r[H - 1] = f2fma(f2sub(FH.x, Fp.x), nd, r[H - 1]);
        m[H - 1] = f2fma(f2sub(FH.y, Fp.y), nd, m[H - 1]);
        E[H - 1] = f2fma(f2sub(FH.z, Fp.z), nd, E[H - 1]);

        if (s + 1 < NSTEPS) {
            if (tid == 0)
                __stcg(&g_haloL[rb ^ 1][b],
                       make_float4(lo2(r[0]), lo2(m[0]), lo2(E[0]), 0.0f));
            if (tid == TPB - 1) {
                __stcg(&g_haloR[rb ^ 1][b],
                       make_float4(hi2(r[H - 1]), hi2(m[H - 1]), hi2(E[H - 1]), 0.0f));
                __threadfence();
            }
            // Publish new last-cell derived pair. Read next step after its
            // Stage-1 sync; overwritten only after next step's Stage-3 sync.
            Cell2 Dn = derive2(r[H - 1], m[H - 1], E[H - 1]);
            sdr[tid] = Dn.r; sdm[tid] = Dn.m; sdE[tid] = Dn.E; sdu[tid] = Dn.u;
            sdp[tid] = Dn.p; sdq[tid] = Dn.q; sdh[tid] = Dn.H;
        }
    }

    // ---- final: conserved -> primitives, both lanes ----
#pragma unroll
    for (int k = 0; k < H; k++) {
        float rl, rh, ml, mh, El, Eh;
        up2(r[k], rl, rh); up2(m[k], ml, mh); up2(E[k], El, Eh);
        float sl = rsqrtf(rl), sh = rsqrtf(rh);
        float il = sl * sl, ih = sh * sh;
        float ul = ml * il, uh = mh * ih;
        out[iL + k] = rl;
        out[n + iL + k] = ul;
        out[2 * n + iL + k] = 0.4f * (El - 0.5f * ml * ul);
        out[iH + k] = rh;
        out[n + iH + k] = uh;
        out[2 * n + iH + k] = 0.4f * (Eh - 0.5f * mh * uh);
    }
}

__global__ void __launch_bounds__(TPB, 1) euler_kernel(
    const float* __restrict__ rho, const float* __restrict__ uin,
    const float* __restrict__ pin,
    float* __restrict__ out, int n) {
    __shared__ ull sdr[TPB], sdm[TPB], sdE[TPB], sdu[TPB],
                   sdp[TPB], sdq[TPB], sdh[TPB];
    __shared__ ull sfx[TPB], sfy[TPB], sfz[TPB];
    __shared__ unsigned int swm[TPB / 32];
    __shared__ float s_dt;

    const int b = blockIdx.x;
    if (b < NBH7) {
        int bb = b * (TPB * 14);
        run_solver<7>(rho, uin, pin, out, n, bb, b,
                      sdr, sdm, sdE, sdu, sdp, sdq, sdh, sfx, sfy, sfz, swm, &s_dt);
    } else {
        int bb = NBH7 * (TPB * 14) + (b - NBH7) * (TPB * 12);
        run_solver<6>(rho, uin, pin, out, n, bb, b,
                      sdr, sdm, sdE, sdu, sdp, sdq, sdh, sfx, sfy, sfz, swm, &s_dt);
    }
}

extern "C" void kernel_launch(void* const* d_in, const int* in_sizes, int n_in,
                              void* d_out, int out_size) {
    const float* rho = (const float*)d_in[0];
    const float* u = (const float*)d_in[1];
    const float* p = (const float*)d_in[2];
    const float* tf = (const float*)d_in[3];
    float* out = (float*)d_out;
    int n = in_sizes[0];
    if (n != NXFIX) return;   // problem is fixed at NX = 2^20

    pre_kernel<<<1, 1>>>(tf);
    euler_kernel<<<NBLK, TPB>>>(rho, u, p, out, n);
}